// round 2
// baseline (speedup 1.0000x reference)
#include <cuda_runtime.h>

// Problem constants (fixed shapes from reference setup_inputs)
#define NTOK   16384      // B*T = 4*4096
#define DDIM   2048
#define NEXP   16
#define NGROUP 4096       // 4 tokens per group
#define GRID_MAIN 152
#define BLOCK_MAIN 256

__device__ float g_wn[NEXP * DDIM];   // noisy weight [E][D]
__device__ float g_bn[NEXP];          // noisy bias
__device__ float g_zp[NGROUP];        // per-group z-loss partials (deterministic slots)

typedef unsigned long long u64;

__device__ __forceinline__ float fnoise(float x) {
    return copysignf(sqrtf(fabsf(x)), x);
}

// packed fp32x2 FMA: d = a*b + d  (SASS FFMA2, 2x fp32 throughput on sm_103a)
__device__ __forceinline__ void ffma2(u64 &d, u64 a, u64 b) {
    asm("fma.rn.f32x2 %0, %1, %2, %0;" : "+l"(d) : "l"(a), "l"(b));
}

__device__ __forceinline__ float2 unpack64(u64 v) {
    float2 r;
    asm("mov.b64 {%0, %1}, %2;" : "=f"(r.x), "=f"(r.y) : "l"(v));
    return r;
}

// ---------------------------------------------------------------------------
// Kernel 1: w_noisy = W + sigma_W * f(eps_out) f(eps_in)^T ;  b_noisy
// ---------------------------------------------------------------------------
__global__ void prep_kernel(const float* __restrict__ w,  const float* __restrict__ sw,
                            const float* __restrict__ b,  const float* __restrict__ sb,
                            const float* __restrict__ ei, const float* __restrict__ eo) {
    int i = blockIdx.x * blockDim.x + threadIdx.x;
    if (i < NEXP * DDIM) {
        int e = i >> 11;          // / 2048
        int d = i & (DDIM - 1);
        g_wn[i] = w[i] + sw[i] * fnoise(eo[e]) * fnoise(ei[d]);
    }
    if (i < NEXP) {
        g_bn[i] = b[i] + sb[i] * fnoise(eo[i]);
    }
}

// ---------------------------------------------------------------------------
// Kernel 2: persistent main kernel.
//   - w_noisy [16][2048] fp32 staged in 128KB SMEM (1 CTA/SM)
//   - each warp handles 4 tokens per group; lane owns 4 consecutive d per
//     128-wide chunk; FFMA2 packed accumulation (acc[t][e] = packed f32x2)
//   - butterfly cross-lane reduce -> 16 logits/token on all lanes
//   - in-register top-2, softmax, z-loss
// ---------------------------------------------------------------------------
__global__ void __launch_bounds__(BLOCK_MAIN, 1)
router_kernel(const float* __restrict__ x, float* __restrict__ out) {
    extern __shared__ float smem[];
    float* w_s = smem;               // 32768 floats
    float* b_s = smem + NEXP * DDIM; // 16 floats

    // cooperative staged load of w_noisy (float4, coalesced)
    {
        const float4* src = (const float4*)g_wn;
        float4* dst = (float4*)w_s;
        for (int i = threadIdx.x; i < (NEXP * DDIM) / 4; i += BLOCK_MAIN)
            dst[i] = src[i];
        if (threadIdx.x < NEXP) b_s[threadIdx.x] = g_bn[threadIdx.x];
    }
    __syncthreads();

    const int lane = threadIdx.x & 31;
    const int wid  = threadIdx.x >> 5;
    const int gw   = blockIdx.x * (BLOCK_MAIN / 32) + wid;   // global warp id
    const int sub  = lane & 7;   // 0..7  (which output pair within token)
    const int tt   = lane >> 3;  // 0..3  (which token this lane writes)

    float* idx_out = out + (size_t)NTOK * NEXP;   // indices region (as float)

    for (int g = gw; g < NGROUP; g += GRID_MAIN * (BLOCK_MAIN / 32)) {
        const int t0 = g * 4;
        const float* xb = x + (size_t)t0 * DDIM + lane * 4;

        u64 acc[4][NEXP];
        #pragma unroll
        for (int t = 0; t < 4; t++)
            #pragma unroll
            for (int e = 0; e < NEXP; e++) acc[t][e] = 0ULL;

        // prefetch chunk 0 (lane's float4 of x for each of 4 tokens)
        ulonglong2 xa[4];
        #pragma unroll
        for (int t = 0; t < 4; t++)
            xa[t] = *(const ulonglong2*)(xb + t * DDIM);

        // 16 chunks of 128 d-values
        for (int c = 0; c < 16; c++) {
            ulonglong2 xn[4];
            if (c < 15) {
                #pragma unroll
                for (int t = 0; t < 4; t++)
                    xn[t] = *(const ulonglong2*)(xb + t * DDIM + (c + 1) * 128);
            }
            const float* wc = w_s + c * 128 + lane * 4;
            #pragma unroll
            for (int e = 0; e < NEXP; e++) {
                ulonglong2 w2 = *(const ulonglong2*)(wc + e * DDIM);
                #pragma unroll
                for (int t = 0; t < 4; t++) {
                    ffma2(acc[t][e], xa[t].x, w2.x);
                    ffma2(acc[t][e], xa[t].y, w2.y);
                }
            }
            if (c < 15) {
                #pragma unroll
                for (int t = 0; t < 4; t++) xa[t] = xn[t];
            }
        }

        // cross-lane reduction: all lanes end with all 64 sums
        float v[4][NEXP];
        #pragma unroll
        for (int t = 0; t < 4; t++) {
            #pragma unroll
            for (int e = 0; e < NEXP; e++) {
                float2 p = unpack64(acc[t][e]);
                float s = p.x + p.y;
                s += __shfl_xor_sync(0xffffffffu, s, 16);
                s += __shfl_xor_sync(0xffffffffu, s, 8);
                s += __shfl_xor_sync(0xffffffffu, s, 4);
                s += __shfl_xor_sync(0xffffffffu, s, 2);
                s += __shfl_xor_sync(0xffffffffu, s, 1);
                v[t][e] = s;
            }
        }

        // epilogue: top-2, softmax over top-2, z-loss
        float zsum = 0.0f;
        #pragma unroll
        for (int t = 0; t < 4; t++) {
            float m1 = -1e30f, m2 = -1e30f;
            int i1 = 0, i2 = 0;
            float l[NEXP];
            #pragma unroll
            for (int e = 0; e < NEXP; e++) {
                l[e] = v[t][e] + b_s[e];
                if (l[e] > m1)      { m2 = m1; i2 = i1; m1 = l[e]; i1 = e; }
                else if (l[e] > m2) { m2 = l[e]; i2 = e; }
            }
            float ez = __expf(m2 - m1);
            float rz = 1.0f / (1.0f + ez);
            float p1 = rz;
            float p2 = ez * rz;

            if (tt == t) {
                int e0 = sub * 2;
                float q0 = (e0     == i1) ? p1 : ((e0     == i2) ? p2 : 0.0f);
                float q1 = (e0 + 1 == i1) ? p1 : ((e0 + 1 == i2) ? p2 : 0.0f);
                *(float2*)(out + (size_t)(t0 + t) * NEXP + e0) = make_float2(q0, q1);
                if (sub == 0) idx_out[(size_t)(t0 + t) * 2 + 0] = (float)i1;
                if (sub == 1) idx_out[(size_t)(t0 + t) * 2 + 1] = (float)i2;
            }
            if (lane == 0) {
                float lse = m1 + log1pf(ez);   // logsumexp(top2)
                zsum += lse * lse;
            }
        }
        if (lane == 0) g_zp[g] = zsum;
    }
}

// ---------------------------------------------------------------------------
// Kernel 3: deterministic z-loss reduction over the 4096 fixed slots
// ---------------------------------------------------------------------------
__global__ void zred_kernel(float* __restrict__ out) {
    __shared__ float s[256];
    float a = 0.0f;
    for (int j = threadIdx.x; j < NGROUP; j += 256) a += g_zp[j];
    s[threadIdx.x] = a;
    __syncthreads();
    for (int k = 128; k > 0; k >>= 1) {
        if (threadIdx.x < k) s[threadIdx.x] += s[threadIdx.x + k];
        __syncthreads();
    }
    if (threadIdx.x == 0)
        out[(size_t)NTOK * NEXP + (size_t)NTOK * 2] = s[0] * (1.0f / (float)NTOK);
}

// ---------------------------------------------------------------------------
extern "C" void kernel_launch(void* const* d_in, const int* in_sizes, int n_in,
                              void* d_out, int out_size) {
    const float* x  = (const float*)d_in[0];  // mh_output [4,4096,2048]
    const float* w  = (const float*)d_in[1];  // weight [16,2048]
    const float* sw = (const float*)d_in[2];  // sigma_weight
    const float* b  = (const float*)d_in[3];  // bias [16]
    const float* sb = (const float*)d_in[4];  // sigma_bias
    const float* ei = (const float*)d_in[5];  // eps_in [2048]
    const float* eo = (const float*)d_in[6];  // eps_out [16]
    float* out = (float*)d_out;

    prep_kernel<<<(NEXP * DDIM + 255) / 256, 256>>>(w, sw, b, sb, ei, eo);

    const size_t smem_bytes = (size_t)(NEXP * DDIM + 16) * sizeof(float);
    cudaFuncSetAttribute(router_kernel,
                         cudaFuncAttributeMaxDynamicSharedMemorySize,
                         (int)smem_bytes);
    router_kernel<<<GRID_MAIN, BLOCK_MAIN, smem_bytes>>>(x, out);

    zred_kernel<<<1, 256>>>(out);
}

// round 5
// speedup vs baseline: 1.2367x; 1.2367x over previous
#include <cuda_runtime.h>

// Shapes fixed by reference setup_inputs
#define NTOK   16384      // B*T = 4*4096
#define DDIM   2048
#define NEXP   16
#define NGROUP 4096       // 4 tokens per group
#define GRID_MAIN 148
#define BLOCK_MAIN 512
#define WARPS_CTA (BLOCK_MAIN / 32)

__device__ float g_zp[NGROUP];        // per-group z-loss partials (deterministic slots)

typedef unsigned long long u64;

__device__ __forceinline__ float fnoise(float x) {
    return copysignf(sqrtf(fabsf(x)), x);
}

// packed fp32x2 FMA: d = a*b + d  (SASS FFMA2, 2x fp32 throughput on sm_103a)
__device__ __forceinline__ void ffma2(u64 &d, u64 a, u64 b) {
    asm("fma.rn.f32x2 %0, %1, %2, %0;" : "+l"(d) : "l"(a), "l"(b));
}

__device__ __forceinline__ u64 pack2(float lo, float hi) {
    u64 r;
    asm("mov.b64 %0, {%1, %2};" : "=l"(r) : "f"(lo), "f"(hi));
    return r;
}

__device__ __forceinline__ float2 unpack64(u64 v) {
    float2 r;
    asm("mov.b64 {%0, %1}, %2;" : "=f"(r.x), "=f"(r.y) : "l"(v));
    return r;
}

// ---------------------------------------------------------------------------
// Persistent main kernel (512 threads, 1 CTA/SM):
//   - noisy-weight fused into the SMEM fill (no separate prep kernel)
//   - w_noisy [16][2048] fp32 in 128KB SMEM, row-major (conflict-free LDS.128)
//   - each warp: 4 tokens as 2 token-PAIRS; acc[pair][expert] packed f32x2
//     (64 regs of accumulators -> fits 512 threads @ <=128 regs)
//   - per (e, d): w broadcast-packed (w,w) on alu pipe, 2 FFMA2 on fma pipe
//   - butterfly reduce, in-register top-2 + softmax + z-loss epilogue
// ---------------------------------------------------------------------------
__global__ void __launch_bounds__(BLOCK_MAIN, 1)
router_kernel(const float* __restrict__ x,
              const float* __restrict__ w,  const float* __restrict__ sw,
              const float* __restrict__ b,  const float* __restrict__ sb,
              const float* __restrict__ ei, const float* __restrict__ eo,
              float* __restrict__ out) {
    extern __shared__ float smem[];
    float* w_s = smem;                       // 32768 floats (128KB)
    float* fi_s = smem + NEXP * DDIM;        // 2048 floats: f(eps_in)
    float* b_s  = fi_s + DDIM;               // 16 floats: b_noisy
    float* fo_s = b_s + NEXP;                // 16 floats: f(eps_out)

    // --- stage 0: noise factors ---
    for (int i = threadIdx.x; i < DDIM; i += BLOCK_MAIN) fi_s[i] = fnoise(ei[i]);
    if (threadIdx.x < NEXP) {
        float fo = fnoise(eo[threadIdx.x]);
        fo_s[threadIdx.x] = fo;
        b_s[threadIdx.x] = b[threadIdx.x] + sb[threadIdx.x] * fo;
    }
    __syncthreads();

    // --- stage 1: w_noisy = W + sigma_W * fo * fi, vectorized fill ---
    {
        const float4* wv  = (const float4*)w;
        const float4* swv = (const float4*)sw;
        float4* dst = (float4*)w_s;
        for (int i4 = threadIdx.x; i4 < (NEXP * DDIM) / 4; i4 += BLOCK_MAIN) {
            int i = i4 * 4;
            int e = i >> 11;            // /2048
            int d = i & (DDIM - 1);
            float fo = fo_s[e];
            float4 a = wv[i4], s = swv[i4], r;
            r.x = a.x + s.x * fo * fi_s[d + 0];
            r.y = a.y + s.y * fo * fi_s[d + 1];
            r.z = a.z + s.z * fo * fi_s[d + 2];
            r.w = a.w + s.w * fo * fi_s[d + 3];
            dst[i4] = r;
        }
    }
    __syncthreads();

    const int lane = threadIdx.x & 31;
    const int wid  = threadIdx.x >> 5;
    const int gw   = blockIdx.x * WARPS_CTA + wid;       // global warp id
    const int sub  = lane & 7;   // which output pair within token
    const int tt   = lane >> 3;  // which token this lane writes

    float* idx_out = out + (size_t)NTOK * NEXP;

    for (int g = gw; g < NGROUP; g += GRID_MAIN * WARPS_CTA) {
        const int t0 = g * 4;
        const float* xb = x + (size_t)t0 * DDIM + lane * 4;

        u64 acc[2][NEXP];
        #pragma unroll
        for (int p = 0; p < 2; p++)
            #pragma unroll
            for (int e = 0; e < NEXP; e++) acc[p][e] = 0ULL;

        // prefetch chunk 0 x (float4 per token)
        float4 xa0 = *(const float4*)(xb + 0 * DDIM);
        float4 xa1 = *(const float4*)(xb + 1 * DDIM);
        float4 xa2 = *(const float4*)(xb + 2 * DDIM);
        float4 xa3 = *(const float4*)(xb + 3 * DDIM);

        #pragma unroll 1
        for (int c = 0; c < 16; c++) {
            // build token-pair packs; xa regs then freed for next-chunk prefetch
            u64 xp0[4], xp1[4];
            xp0[0] = pack2(xa0.x, xa1.x); xp1[0] = pack2(xa2.x, xa3.x);
            xp0[1] = pack2(xa0.y, xa1.y); xp1[1] = pack2(xa2.y, xa3.y);
            xp0[2] = pack2(xa0.z, xa1.z); xp1[2] = pack2(xa2.z, xa3.z);
            xp0[3] = pack2(xa0.w, xa1.w); xp1[3] = pack2(xa2.w, xa3.w);

            if (c < 15) {
                const float* xn = xb + (c + 1) * 128;
                xa0 = *(const float4*)(xn + 0 * DDIM);
                xa1 = *(const float4*)(xn + 1 * DDIM);
                xa2 = *(const float4*)(xn + 2 * DDIM);
                xa3 = *(const float4*)(xn + 3 * DDIM);
            }

            const float* wc = w_s + c * 128 + lane * 4;
            #pragma unroll
            for (int e = 0; e < NEXP; e++) {
                float4 w4 = *(const float4*)(wc + e * DDIM);
                u64 wb;
                wb = pack2(w4.x, w4.x); ffma2(acc[0][e], xp0[0], wb); ffma2(acc[1][e], xp1[0], wb);
                wb = pack2(w4.y, w4.y); ffma2(acc[0][e], xp0[1], wb); ffma2(acc[1][e], xp1[1], wb);
                wb = pack2(w4.z, w4.z); ffma2(acc[0][e], xp0[2], wb); ffma2(acc[1][e], xp1[2], wb);
                wb = pack2(w4.w, w4.w); ffma2(acc[0][e], xp0[3], wb); ffma2(acc[1][e], xp1[3], wb);
            }
        }

        // cross-lane reduction: all lanes end with all 64 logit partial sums
        float v[4][NEXP];
        #pragma unroll
        for (int p = 0; p < 2; p++) {
            #pragma unroll
            for (int e = 0; e < NEXP; e++) {
                float2 q = unpack64(acc[p][e]);
                float s0 = q.x, s1 = q.y;
                #pragma unroll
                for (int k = 16; k > 0; k >>= 1) {
                    s0 += __shfl_xor_sync(0xffffffffu, s0, k);
                    s1 += __shfl_xor_sync(0xffffffffu, s1, k);
                }
                v[2 * p + 0][e] = s0;
                v[2 * p + 1][e] = s1;
            }
        }

        // epilogue: top-2, softmax over top-2, z-loss
        float zsum = 0.0f;
        #pragma unroll
        for (int t = 0; t < 4; t++) {
            float m1 = -1e30f, m2 = -1e30f;
            int i1 = 0, i2 = 0;
            #pragma unroll
            for (int e = 0; e < NEXP; e++) {
                float le = v[t][e] + b_s[e];
                if (le > m1)      { m2 = m1; i2 = i1; m1 = le; i1 = e; }
                else if (le > m2) { m2 = le; i2 = e; }
            }
            float ez = __expf(m2 - m1);
            float rz = 1.0f / (1.0f + ez);
            float p1 = rz;
            float p2 = ez * rz;

            if (tt == t) {
                int e0 = sub * 2;
                float q0 = (e0     == i1) ? p1 : ((e0     == i2) ? p2 : 0.0f);
                float q1 = (e0 + 1 == i1) ? p1 : ((e0 + 1 == i2) ? p2 : 0.0f);
                *(float2*)(out + (size_t)(t0 + t) * NEXP + e0) = make_float2(q0, q1);
                if (sub == 0) idx_out[(size_t)(t0 + t) * 2 + 0] = (float)i1;
                if (sub == 1) idx_out[(size_t)(t0 + t) * 2 + 1] = (float)i2;
            }
            if (lane == 0) {
                float lse = m1 + log1pf(ez);   // logsumexp(top2)
                zsum += lse * lse;
            }
        }
        if (lane == 0) g_zp[g] = zsum;
    }
}

// ---------------------------------------------------------------------------
// Deterministic z-loss reduction over the 4096 fixed slots
// ---------------------------------------------------------------------------
__global__ void zred_kernel(float* __restrict__ out) {
    __shared__ float s[256];
    float a = 0.0f;
    for (int j = threadIdx.x; j < NGROUP; j += 256) a += g_zp[j];
    s[threadIdx.x] = a;
    __syncthreads();
    for (int k = 128; k > 0; k >>= 1) {
        if (threadIdx.x < k) s[threadIdx.x] += s[threadIdx.x + k];
        __syncthreads();
    }
    if (threadIdx.x == 0)
        out[(size_t)NTOK * NEXP + (size_t)NTOK * 2] = s[0] * (1.0f / (float)NTOK);
}

// ---------------------------------------------------------------------------
extern "C" void kernel_launch(void* const* d_in, const int* in_sizes, int n_in,
                              void* d_out, int out_size) {
    const float* x  = (const float*)d_in[0];  // mh_output [4,4096,2048]
    const float* w  = (const float*)d_in[1];  // weight [16,2048]
    const float* sw = (const float*)d_in[2];  // sigma_weight
    const float* b  = (const float*)d_in[3];  // bias [16]
    const float* sb = (const float*)d_in[4];  // sigma_bias
    const float* ei = (const float*)d_in[5];  // eps_in [2048]
    const float* eo = (const float*)d_in[6];  // eps_out [16]
    float* out = (float*)d_out;

    const size_t smem_bytes = (size_t)(NEXP * DDIM + DDIM + 2 * NEXP) * sizeof(float);
    cudaFuncSetAttribute(router_kernel,
                         cudaFuncAttributeMaxDynamicSharedMemorySize,
                         (int)smem_bytes);
    router_kernel<<<GRID_MAIN, BLOCK_MAIN, smem_bytes>>>(x, w, sw, b, sb, ei, eo, out);

    zred_kernel<<<1, 256>>>(out);
}

// round 9
// speedup vs baseline: 1.2784x; 1.0338x over previous
#include <cuda_runtime.h>

// Shapes fixed by reference setup_inputs
#define NTOK   16384      // B*T = 4*4096
#define DDIM   2048
#define NEXP   16
#define NPAIR  8          // expert pairs packed into f32x2 halves
#define NGROUP 4096       // 4 tokens per group
#define GRID_MAIN 148
#define BLOCK_MAIN 448    // 14 warps -> 2072 warps total, ~98.8% group-slot fill
#define WARPS_CTA (BLOCK_MAIN / 32)
#define TOTAL_WARPS (GRID_MAIN * WARPS_CTA)

__device__ float g_zp[GRID_MAIN];     // per-CTA z-loss partials (deterministic)
__device__ unsigned int g_ctr;        // last-CTA ticket (reset each launch)

typedef unsigned long long u64;

__device__ __forceinline__ float fnoise(float x) {
    return copysignf(sqrtf(fabsf(x)), x);
}
// packed fp32x2 FMA: d = a*b + d
__device__ __forceinline__ void ffma2(u64 &d, u64 a, u64 b) {
    asm("fma.rn.f32x2 %0, %1, %2, %0;" : "+l"(d) : "l"(a), "l"(b));
}
__device__ __forceinline__ u64 addx2(u64 a, u64 b) {
    u64 r; asm("add.rn.f32x2 %0, %1, %2;" : "=l"(r) : "l"(a), "l"(b)); return r;
}
__device__ __forceinline__ u64 pack2(float lo, float hi) {
    u64 r; asm("mov.b64 %0, {%1, %2};" : "=l"(r) : "f"(lo), "f"(hi)); return r;
}
__device__ __forceinline__ float2 unpack64(u64 v) {
    float2 r; asm("mov.b64 {%0, %1}, %2;" : "=f"(r.x), "=f"(r.y) : "l"(v)); return r;
}

// ---------------------------------------------------------------------------
// Single persistent kernel.
//   SMEM weights pre-interleaved by EXPERT PAIR:
//     w2[p][d] = (w_noisy[2p][d], w_noisy[2p+1][d])  as u64,
//   stored with a half-chunk re-index so the mainloop's LDS.128 has lane
//   stride 16B (conflict-free):
//     storage u64 index = p*2048 + c*128 + (k>>1)*64 + l*2 + (k&1)
//     where d = c*128 + l*4 + k.
//   Mainloop: zero MOVs for w (LDS.128 yields both experts x two d),
//   x broadcast-packed (x,x) once per (token,d).  acc[4 tok][8 pairs] u64.
//   z-loss fully fused via last-CTA reduction (no second kernel).
// ---------------------------------------------------------------------------
__global__ void __launch_bounds__(BLOCK_MAIN, 1)
router_kernel(const float* __restrict__ x,
              const float* __restrict__ w,  const float* __restrict__ sw,
              const float* __restrict__ b,  const float* __restrict__ sb,
              const float* __restrict__ ei, const float* __restrict__ eo,
              float* __restrict__ out) {
    extern __shared__ __align__(16) char smem_raw[];
    u64*   w2_s = (u64*)smem_raw;                  // 8*2048 u64 = 128KB
    float* fi_s = (float*)(w2_s + NPAIR * DDIM);   // 2048
    float* fo_s = fi_s + DDIM;                     // 16
    float* b_s  = fo_s + NEXP;                     // 16
    float* z_s  = b_s + NEXP;                      // WARPS_CTA

    // --- stage 0: noise factors ---
    for (int i = threadIdx.x; i < DDIM; i += BLOCK_MAIN) fi_s[i] = fnoise(ei[i]);
    if (threadIdx.x < NEXP) {
        float fo = fnoise(eo[threadIdx.x]);
        fo_s[threadIdx.x] = fo;
        b_s[threadIdx.x] = b[threadIdx.x] + sb[threadIdx.x] * fo;
    }
    __syncthreads();

    // --- stage 1: noisy weights, expert-pair interleaved + half-chunk swizzle ---
    for (int it = threadIdx.x; it < NPAIR * (DDIM / 2); it += BLOCK_MAIN) {
        int p = it >> 10;            // pair
        int d = (it & 1023) * 2;     // even d; handles d, d+1
        int e0 = 2 * p, e1 = 2 * p + 1;
        float2 w0 = *(const float2*)(w  + e0 * DDIM + d);
        float2 w1 = *(const float2*)(w  + e1 * DDIM + d);
        float2 s0 = *(const float2*)(sw + e0 * DDIM + d);
        float2 s1 = *(const float2*)(sw + e1 * DDIM + d);
        float2 fi = *(const float2*)(fi_s + d);
        float f0 = fo_s[e0], f1 = fo_s[e1];
        float a00 = w0.x + s0.x * f0 * fi.x;   // e0, d
        float a01 = w0.y + s0.y * f0 * fi.y;   // e0, d+1
        float a10 = w1.x + s1.x * f1 * fi.x;   // e1, d
        float a11 = w1.y + s1.y * f1 * fi.y;   // e1, d+1
        int c = d >> 7, r = d & 127, l = r >> 2, k = r & 3;   // k in {0,2}
        int sidx = p * 2048 + c * 128 + (k >> 1) * 64 + l * 2;
        ulonglong2 st;
        st.x = pack2(a00, a10);    // (e0,e1) at d
        st.y = pack2(a01, a11);    // (e0,e1) at d+1
        *(ulonglong2*)(w2_s + sidx) = st;
    }
    __syncthreads();

    const int lane = threadIdx.x & 31;
    const int wid  = threadIdx.x >> 5;
    const int gw   = blockIdx.x * WARPS_CTA + wid;
    const int sub  = lane & 7;
    const int tt   = lane >> 3;

    float* idx_out = out + (size_t)NTOK * NEXP;
    float zsum = 0.0f;

    for (int g = gw; g < NGROUP; g += TOTAL_WARPS) {
        const int t0 = g * 4;
        const float* xb = x + (size_t)t0 * DDIM + lane * 4;

        u64 acc[4][NPAIR];
        #pragma unroll
        for (int t = 0; t < 4; t++)
            #pragma unroll
            for (int p = 0; p < NPAIR; p++) acc[t][p] = 0ULL;

        // prefetch chunk 0
        float4 xa0 = *(const float4*)(xb + 0 * DDIM);
        float4 xa1 = *(const float4*)(xb + 1 * DDIM);
        float4 xa2 = *(const float4*)(xb + 2 * DDIM);
        float4 xa3 = *(const float4*)(xb + 3 * DDIM);

        #pragma unroll 1
        for (int c = 0; c < 16; c++) {
            // broadcast-pack x components (frees xa for next prefetch)
            u64 xk0[4], xk1[4], xk2[4], xk3[4];
            xk0[0] = pack2(xa0.x, xa0.x); xk1[0] = pack2(xa0.y, xa0.y);
            xk2[0] = pack2(xa0.z, xa0.z); xk3[0] = pack2(xa0.w, xa0.w);
            xk0[1] = pack2(xa1.x, xa1.x); xk1[1] = pack2(xa1.y, xa1.y);
            xk2[1] = pack2(xa1.z, xa1.z); xk3[1] = pack2(xa1.w, xa1.w);
            xk0[2] = pack2(xa2.x, xa2.x); xk1[2] = pack2(xa2.y, xa2.y);
            xk2[2] = pack2(xa2.z, xa2.z); xk3[2] = pack2(xa2.w, xa2.w);
            xk0[3] = pack2(xa3.x, xa3.x); xk1[3] = pack2(xa3.y, xa3.y);
            xk2[3] = pack2(xa3.z, xa3.z); xk3[3] = pack2(xa3.w, xa3.w);

            if (c < 15) {
                const float* xn = xb + (c + 1) * 128;
                xa0 = *(const float4*)(xn + 0 * DDIM);
                xa1 = *(const float4*)(xn + 1 * DDIM);
                xa2 = *(const float4*)(xn + 2 * DDIM);
                xa3 = *(const float4*)(xn + 3 * DDIM);
            }

            const u64* wc = w2_s + c * 128 + lane * 2;
            #pragma unroll
            for (int p = 0; p < NPAIR; p++) {
                // wA = (e-pair at d=4l, d=4l+1), wB = (e-pair at d=4l+2, 4l+3)
                ulonglong2 wA = *(const ulonglong2*)(wc + p * 2048);
                ulonglong2 wB = *(const ulonglong2*)(wc + p * 2048 + 64);
                #pragma unroll
                for (int t = 0; t < 4; t++) {
                    ffma2(acc[t][p], xk0[t], wA.x);
                    ffma2(acc[t][p], xk1[t], wA.y);
                    ffma2(acc[t][p], xk2[t], wB.x);
                    ffma2(acc[t][p], xk3[t], wB.y);
                }
            }
        }

        // cross-lane reduction (packed): every lane gets all 64 logit sums
        float v[4][NEXP];
        #pragma unroll
        for (int t = 0; t < 4; t++) {
            #pragma unroll
            for (int p = 0; p < NPAIR; p++) {
                u64 s = acc[t][p];
                #pragma unroll
                for (int k = 16; k > 0; k >>= 1)
                    s = addx2(s, __shfl_xor_sync(0xffffffffu, s, k));
                float2 q = unpack64(s);
                v[t][2 * p + 0] = q.x;
                v[t][2 * p + 1] = q.y;
            }
        }

        // epilogue: top-2, softmax over top-2, z-loss
        #pragma unroll
        for (int t = 0; t < 4; t++) {
            float m1 = -1e30f, m2 = -1e30f;
            int i1 = 0, i2 = 0;
            #pragma unroll
            for (int e = 0; e < NEXP; e++) {
                float le = v[t][e] + b_s[e];
                if (le > m1)      { m2 = m1; i2 = i1; m1 = le; i1 = e; }
                else if (le > m2) { m2 = le; i2 = e; }
            }
            float ez = __expf(m2 - m1);
            float rz = 1.0f / (1.0f + ez);
            float p1 = rz;
            float p2 = ez * rz;

            if (tt == t) {
                int e0 = sub * 2;
                float q0 = (e0     == i1) ? p1 : ((e0     == i2) ? p2 : 0.0f);
                float q1 = (e0 + 1 == i1) ? p1 : ((e0 + 1 == i2) ? p2 : 0.0f);
                *(float2*)(out + (size_t)(t0 + t) * NEXP + e0) = make_float2(q0, q1);
                if (sub == 0) idx_out[(size_t)(t0 + t) * 2 + 0] = (float)i1;
                if (sub == 1) idx_out[(size_t)(t0 + t) * 2 + 1] = (float)i2;
            }
            if (lane == 0) {
                float lse = m1 + log1pf(ez);   // logsumexp(top2)
                zsum += lse * lse;
            }
        }
    }

    // --- fused z-loss reduction: CTA partial, then last-CTA finishes ---
    if (lane == 0) z_s[wid] = zsum;
    __syncthreads();
    __shared__ unsigned int s_last;
    if (threadIdx.x == 0) {
        float a = 0.0f;
        #pragma unroll
        for (int i = 0; i < WARPS_CTA; i++) a += z_s[i];
        g_zp[blockIdx.x] = a;
        __threadfence();
        unsigned int ticket = atomicAdd(&g_ctr, 1u);
        s_last = (ticket == GRID_MAIN - 1) ? 1u : 0u;
    }
    __syncthreads();
    if (s_last && wid == 0) {
        float a = 0.0f;
        for (int i = lane; i < GRID_MAIN; i += 32) a += __ldcg(&g_zp[i]);
        #pragma unroll
        for (int k = 16; k > 0; k >>= 1)
            a += __shfl_xor_sync(0xffffffffu, a, k);
        if (lane == 0) {
            out[(size_t)NTOK * NEXP + (size_t)NTOK * 2] = a * (1.0f / (float)NTOK);
            g_ctr = 0;   // reset for next launch / graph replay
        }
    }
}

// ---------------------------------------------------------------------------
extern "C" void kernel_launch(void* const* d_in, const int* in_sizes, int n_in,
                              void* d_out, int out_size) {
    const float* x  = (const float*)d_in[0];  // mh_output [4,4096,2048]
    const float* w  = (const float*)d_in[1];  // weight [16,2048]
    const float* sw = (const float*)d_in[2];  // sigma_weight
    const float* b  = (const float*)d_in[3];  // bias [16]
    const float* sb = (const float*)d_in[4];  // sigma_bias
    const float* ei = (const float*)d_in[5];  // eps_in [2048]
    const float* eo = (const float*)d_in[6];  // eps_out [16]
    float* out = (float*)d_out;

    const size_t smem_bytes = (size_t)NPAIR * DDIM * sizeof(u64)
                            + (size_t)(DDIM + 2 * NEXP + WARPS_CTA) * sizeof(float)
                            + 64;
    cudaFuncSetAttribute(router_kernel,
                         cudaFuncAttributeMaxDynamicSharedMemorySize,
                         (int)smem_bytes);
    router_kernel<<<GRID_MAIN, BLOCK_MAIN, smem_bytes>>>(x, w, sw, b, sb, ei, eo, out);
}

// round 11
// speedup vs baseline: 1.3097x; 1.0245x over previous
#include <cuda_runtime.h>

// Shapes fixed by reference setup_inputs
#define NTOK   16384      // B*T
#define DDIM   2048
#define NEXP   16
#define NPAIR  8
#define NGROUP 4096       // 4 tokens per group
#define GRID_MAIN 148
#define BLOCK_MAIN 448
#define WARPS_CTA 14
#define TOTAL_WARPS (GRID_MAIN * WARPS_CTA)
#define STAGES 3          // cp.async pipeline depth

#define W2_BYTES   (NPAIR * DDIM * 8)             // 131072
#define XSTG_BYTES (WARPS_CTA * STAGES * 2048)    // 86016 (2KB per warp-stage)

__device__ float g_zp[GRID_MAIN];     // per-CTA z-loss partials (deterministic)
__device__ unsigned int g_ctr;        // last-CTA ticket (reset each launch)

typedef unsigned long long u64;

__device__ __forceinline__ float fnoise(float x) {
    return copysignf(sqrtf(fabsf(x)), x);
}
__device__ __forceinline__ void ffma2(u64 &d, u64 a, u64 b) {
    asm("fma.rn.f32x2 %0, %1, %2, %0;" : "+l"(d) : "l"(a), "l"(b));
}
__device__ __forceinline__ u64 addx2(u64 a, u64 b) {
    u64 r; asm("add.rn.f32x2 %0, %1, %2;" : "=l"(r) : "l"(a), "l"(b)); return r;
}
__device__ __forceinline__ u64 pack2(float lo, float hi) {
    u64 r; asm("mov.b64 %0, {%1, %2};" : "=l"(r) : "f"(lo), "f"(hi)); return r;
}
__device__ __forceinline__ float2 unpack64(u64 v) {
    float2 r; asm("mov.b64 {%0, %1}, %2;" : "=f"(r.x), "=f"(r.y) : "l"(v)); return r;
}
__device__ __forceinline__ unsigned smem_u32(const void* p) {
    return (unsigned)__cvta_generic_to_shared(p);
}
// 16B async copy gmem -> smem (LDGSTS.128). "memory" clobber keeps prior LDS
// reads of the same stage from sinking below the issue.
__device__ __forceinline__ void cp16(unsigned dst, const float* src) {
    asm volatile("cp.async.cg.shared.global [%0], [%1], 16;"
                 :: "r"(dst), "l"(src) : "memory");
}
__device__ __forceinline__ void cp_commit() {
    asm volatile("cp.async.commit_group;" ::: "memory");
}
__device__ __forceinline__ void cp_wait2() {
    asm volatile("cp.async.wait_group 2;" ::: "memory");
}

// ---------------------------------------------------------------------------
// Single persistent kernel, depth-3 cp.async x-pipeline.
//   SMEM: expert-pair-interleaved noisy weights (128KB, conflict-free LDS.128)
//         + per-warp x staging ring (3 stages x 2KB).
//   Per chunk: wait stage -> LDS x -> broadcast-pack -> issue cp.async c+3
//   -> 16 w-LDS.128 + 128 FFMA2.  acc[4 tok][8 pairs] packed f32x2.
//   z-loss fused via last-CTA reduction.
// ---------------------------------------------------------------------------
__global__ void __launch_bounds__(BLOCK_MAIN, 1)
router_kernel(const float* __restrict__ x,
              const float* __restrict__ w,  const float* __restrict__ sw,
              const float* __restrict__ b,  const float* __restrict__ sb,
              const float* __restrict__ ei, const float* __restrict__ eo,
              float* __restrict__ out) {
    extern __shared__ __align__(16) char smem_raw[];
    u64*   w2_s   = (u64*)smem_raw;                         // 128KB
    float* xstage = (float*)(smem_raw + W2_BYTES);          // 84KB
    float* fi_s   = (float*)(smem_raw + W2_BYTES + XSTG_BYTES); // 2048
    float* fo_s   = fi_s + DDIM;                            // 16
    float* b_s    = fo_s + NEXP;                            // 16
    float* z_s    = b_s + NEXP;                             // WARPS_CTA

    // --- stage 0: noise factors ---
    for (int i = threadIdx.x; i < DDIM; i += BLOCK_MAIN) fi_s[i] = fnoise(ei[i]);
    if (threadIdx.x < NEXP) {
        float fo = fnoise(eo[threadIdx.x]);
        fo_s[threadIdx.x] = fo;
        b_s[threadIdx.x] = b[threadIdx.x] + sb[threadIdx.x] * fo;
    }
    __syncthreads();

    // --- stage 1: noisy weights, expert-pair interleaved + half-chunk swizzle ---
    // storage u64 index = p*2048 + c*128 + (k>>1)*64 + l*2 + (k&1),  d = c*128+l*4+k
    for (int it = threadIdx.x; it < NPAIR * (DDIM / 2); it += BLOCK_MAIN) {
        int p = it >> 10;
        int d = (it & 1023) * 2;
        int e0 = 2 * p, e1 = 2 * p + 1;
        float2 w0 = *(const float2*)(w  + e0 * DDIM + d);
        float2 w1 = *(const float2*)(w  + e1 * DDIM + d);
        float2 s0 = *(const float2*)(sw + e0 * DDIM + d);
        float2 s1 = *(const float2*)(sw + e1 * DDIM + d);
        float2 fi = *(const float2*)(fi_s + d);
        float f0 = fo_s[e0], f1 = fo_s[e1];
        float a00 = w0.x + s0.x * f0 * fi.x;
        float a01 = w0.y + s0.y * f0 * fi.y;
        float a10 = w1.x + s1.x * f1 * fi.x;
        float a11 = w1.y + s1.y * f1 * fi.y;
        int c = d >> 7, r = d & 127, l = r >> 2, k = r & 3;
        int sidx = p * 2048 + c * 128 + (k >> 1) * 64 + l * 2;
        ulonglong2 st;
        st.x = pack2(a00, a10);
        st.y = pack2(a01, a11);
        *(ulonglong2*)(w2_s + sidx) = st;
    }
    __syncthreads();

    const int lane = threadIdx.x & 31;
    const int wid  = threadIdx.x >> 5;
    const int gw   = blockIdx.x * WARPS_CTA + wid;
    const int sub  = lane & 7;
    const int tt   = lane >> 3;

    float*   warp_stg = xstage + wid * (STAGES * 512);       // this warp's ring
    unsigned stg_u32  = smem_u32(warp_stg) + lane * 16;      // byte addr, lane slice

    float* idx_out = out + (size_t)NTOK * NEXP;
    float zsum = 0.0f;

    for (int g = gw; g < NGROUP; g += TOTAL_WARPS) {
        const int t0 = g * 4;
        const float* xg = x + (size_t)t0 * DDIM + lane * 4;

        // prime stages 0..2 with chunks 0..2
        #pragma unroll
        for (int s = 0; s < STAGES; s++) {
            #pragma unroll
            for (int t = 0; t < 4; t++)
                cp16(stg_u32 + s * 2048 + t * 512, xg + t * DDIM + s * 128);
            cp_commit();
        }

        u64 acc[4][NPAIR];
        #pragma unroll
        for (int t = 0; t < 4; t++)
            #pragma unroll
            for (int p = 0; p < NPAIR; p++) acc[t][p] = 0ULL;

        int stage = 0;
        #pragma unroll 1
        for (int c = 0; c < 16; c++) {
            cp_wait2();   // chunk c's stage is complete

            const float* xs = warp_stg + stage * 512 + lane * 4;
            float4 xa0 = *(const float4*)(xs + 0 * 128);
            float4 xa1 = *(const float4*)(xs + 1 * 128);
            float4 xa2 = *(const float4*)(xs + 2 * 128);
            float4 xa3 = *(const float4*)(xs + 3 * 128);

            // broadcast-pack x components (consumed before stage is reused)
            u64 xk0[4], xk1[4], xk2[4], xk3[4];
            xk0[0] = pack2(xa0.x, xa0.x); xk1[0] = pack2(xa0.y, xa0.y);
            xk2[0] = pack2(xa0.z, xa0.z); xk3[0] = pack2(xa0.w, xa0.w);
            xk0[1] = pack2(xa1.x, xa1.x); xk1[1] = pack2(xa1.y, xa1.y);
            xk2[1] = pack2(xa1.z, xa1.z); xk3[1] = pack2(xa1.w, xa1.w);
            xk0[2] = pack2(xa2.x, xa2.x); xk1[2] = pack2(xa2.y, xa2.y);
            xk2[2] = pack2(xa2.z, xa2.z); xk3[2] = pack2(xa2.w, xa2.w);
            xk0[3] = pack2(xa3.x, xa3.x); xk1[3] = pack2(xa3.y, xa3.y);
            xk2[3] = pack2(xa3.z, xa3.z); xk3[3] = pack2(xa3.w, xa3.w);

            // refill this stage with chunk c+3 (overlaps the FMA block below)
            if (c < 13) {
                #pragma unroll
                for (int t = 0; t < 4; t++)
                    cp16(stg_u32 + stage * 2048 + t * 512,
                         xg + t * DDIM + (c + 3) * 128);
            }
            cp_commit();   // uniform commit (possibly empty group)

            const u64* wc = w2_s + c * 128 + lane * 2;
            #pragma unroll
            for (int p = 0; p < NPAIR; p++) {
                ulonglong2 wA = *(const ulonglong2*)(wc + p * 2048);
                ulonglong2 wB = *(const ulonglong2*)(wc + p * 2048 + 64);
                #pragma unroll
                for (int t = 0; t < 4; t++) {
                    ffma2(acc[t][p], xk0[t], wA.x);
                    ffma2(acc[t][p], xk1[t], wA.y);
                    ffma2(acc[t][p], xk2[t], wB.x);
                    ffma2(acc[t][p], xk3[t], wB.y);
                }
            }
            stage = (stage == STAGES - 1) ? 0 : stage + 1;
        }

        // cross-lane reduction (packed): every lane gets all 64 logit sums
        float v[4][NEXP];
        #pragma unroll
        for (int t = 0; t < 4; t++) {
            #pragma unroll
            for (int p = 0; p < NPAIR; p++) {
                u64 s = acc[t][p];
                #pragma unroll
                for (int k = 16; k > 0; k >>= 1)
                    s = addx2(s, __shfl_xor_sync(0xffffffffu, s, k));
                float2 q = unpack64(s);
                v[t][2 * p + 0] = q.x;
                v[t][2 * p + 1] = q.y;
            }
        }

        // epilogue: top-2, softmax over top-2, z-loss
        #pragma unroll
        for (int t = 0; t < 4; t++) {
            float m1 = -1e30f, m2 = -1e30f;
            int i1 = 0, i2 = 0;
            #pragma unroll
            for (int e = 0; e < NEXP; e++) {
                float le = v[t][e] + b_s[e];
                if (le > m1)      { m2 = m1; i2 = i1; m1 = le; i1 = e; }
                else if (le > m2) { m2 = le; i2 = e; }
            }
            float ez = __expf(m2 - m1);
            float rz = 1.0f / (1.0f + ez);
            float p1 = rz;
            float p2 = ez * rz;

            if (tt == t) {
                int e0 = sub * 2;
                float q0 = (e0     == i1) ? p1 : ((e0     == i2) ? p2 : 0.0f);
                float q1 = (e0 + 1 == i1) ? p1 : ((e0 + 1 == i2) ? p2 : 0.0f);
                *(float2*)(out + (size_t)(t0 + t) * NEXP + e0) = make_float2(q0, q1);
                if (sub == 0) idx_out[(size_t)(t0 + t) * 2 + 0] = (float)i1;
                if (sub == 1) idx_out[(size_t)(t0 + t) * 2 + 1] = (float)i2;
            }
            if (lane == 0) {
                float lse = m1 + log1pf(ez);
                zsum += lse * lse;
            }
        }
    }

    // --- fused z-loss reduction: CTA partial, then last CTA finishes ---
    if (lane == 0) z_s[wid] = zsum;
    __syncthreads();
    __shared__ unsigned int s_last;
    if (threadIdx.x == 0) {
        float a = 0.0f;
        #pragma unroll
        for (int i = 0; i < WARPS_CTA; i++) a += z_s[i];
        g_zp[blockIdx.x] = a;
        __threadfence();
        unsigned int ticket = atomicAdd(&g_ctr, 1u);
        s_last = (ticket == GRID_MAIN - 1) ? 1u : 0u;
    }
    __syncthreads();
    if (s_last && wid == 0) {
        float a = 0.0f;
        for (int i = lane; i < GRID_MAIN; i += 32) a += __ldcg(&g_zp[i]);
        #pragma unroll
        for (int k = 16; k > 0; k >>= 1)
            a += __shfl_xor_sync(0xffffffffu, a, k);
        if (lane == 0) {
            out[(size_t)NTOK * NEXP + (size_t)NTOK * 2] = a * (1.0f / (float)NTOK);
            g_ctr = 0;   // reset for next launch / graph replay
        }
    }
}

// ---------------------------------------------------------------------------
extern "C" void kernel_launch(void* const* d_in, const int* in_sizes, int n_in,
                              void* d_out, int out_size) {
    const float* x  = (const float*)d_in[0];  // mh_output [4,4096,2048]
    const float* w  = (const float*)d_in[1];  // weight [16,2048]
    const float* sw = (const float*)d_in[2];  // sigma_weight
    const float* b  = (const float*)d_in[3];  // bias [16]
    const float* sb = (const float*)d_in[4];  // sigma_bias
    const float* ei = (const float*)d_in[5];  // eps_in [2048]
    const float* eo = (const float*)d_in[6];  // eps_out [16]
    float* out = (float*)d_out;

    const size_t smem_bytes = (size_t)W2_BYTES + XSTG_BYTES
                            + (size_t)(DDIM + 2 * NEXP + WARPS_CTA) * sizeof(float)
                            + 64;
    cudaFuncSetAttribute(router_kernel,
                         cudaFuncAttributeMaxDynamicSharedMemorySize,
                         (int)smem_bytes);
    router_kernel<<<GRID_MAIN, BLOCK_MAIN, smem_bytes>>>(x, w, sw, b, sb, ei, eo, out);
}

// round 12
// speedup vs baseline: 1.6287x; 1.2435x over previous
#include <cuda_runtime.h>

// Shapes fixed by reference setup_inputs
#define NTOK   16384      // B*T
#define DDIM   2048
#define NEXP   16
#define TOK_W  8          // tokens per warp (one group per warp)
#define NGRP   (NTOK / TOK_W)          // 2048 groups
#define GRID_MAIN 148
#define BLOCK_MAIN 448
#define WARPS_CTA 14
#define NHC    32         // half-chunks of 64 d
#define STAGES 3
#define STG_FLOATS 512    // 8 tok * 64 d floats = 2KB per stage

#define W2_U64     (NEXP/2 * DDIM)                 // 16384 u64 = 128KB
#define XSTG_FLOATS (WARPS_CTA * STAGES * STG_FLOATS)

__device__ float g_zp[GRID_MAIN];     // per-CTA z-loss partials (deterministic)
__device__ unsigned int g_ctr;        // last-CTA ticket (reset each launch)

typedef unsigned long long u64;

__device__ __forceinline__ float fnoise(float x) {
    return copysignf(sqrtf(fabsf(x)), x);
}
__device__ __forceinline__ void ffma2(u64 &d, u64 a, u64 b) {
    asm("fma.rn.f32x2 %0, %1, %2, %0;" : "+l"(d) : "l"(a), "l"(b));
}
__device__ __forceinline__ u64 addx2(u64 a, u64 b) {
    u64 r; asm("add.rn.f32x2 %0, %1, %2;" : "=l"(r) : "l"(a), "l"(b)); return r;
}
__device__ __forceinline__ u64 pack2(float lo, float hi) {
    u64 r; asm("mov.b64 %0, {%1, %2};" : "=l"(r) : "f"(lo), "f"(hi)); return r;
}
__device__ __forceinline__ float2 unpack64(u64 v) {
    float2 r; asm("mov.b64 {%0, %1}, %2;" : "=f"(r.x), "=f"(r.y) : "l"(v)); return r;
}
__device__ __forceinline__ unsigned smem_u32(const void* p) {
    return (unsigned)__cvta_generic_to_shared(p);
}
__device__ __forceinline__ void cp16(unsigned dst, const float* src) {
    asm volatile("cp.async.cg.shared.global [%0], [%1], 16;"
                 :: "r"(dst), "l"(src) : "memory");
}
__device__ __forceinline__ void cp_commit() {
    asm volatile("cp.async.commit_group;" ::: "memory");
}
__device__ __forceinline__ void cp_wait2() {
    asm volatile("cp.async.wait_group 2;" ::: "memory");
}
__device__ __forceinline__ void cp_wait0() {
    asm volatile("cp.async.wait_group 0;" ::: "memory");
}

// ---------------------------------------------------------------------------
// Half-warp expert split, 8 tokens/warp, exactly one group per warp.
//   lanes 0-15 (h=0): experts 0-7 (pairs 0-3); lanes 16-31: experts 8-15.
//   w in SMEM, swizzled so each lane's 16 u64 per half-chunk come from
//   8 conflict-free LDS.128, hoisted into regs before the token loop:
//     u64 slot(P,d) : hc=d>>6, j=(d>>2)&15, q=d&3, h=P>>2, p=P&3,
//                     idx = hc*512 + h*256 + (p*2+(q>>1))*32 + j*2 + (q&1)
//   x staged per warp via depth-3 cp.async (64-d half-chunks, 2KB stages).
//   acc[8 tok][4 pairs] packed f32x2 (e-pair in halves) = 64 regs.
//   Epilogue: half-warp butterfly d-reduce, cross-half swap through the
//   retired x stage, per-lane top-2/softmax, fused last-CTA z-loss.
// ---------------------------------------------------------------------------
__global__ void __launch_bounds__(BLOCK_MAIN, 1)
router_kernel(const float* __restrict__ x,
              const float* __restrict__ w,  const float* __restrict__ sw,
              const float* __restrict__ b,  const float* __restrict__ sb,
              const float* __restrict__ ei, const float* __restrict__ eo,
              float* __restrict__ out) {
    extern __shared__ __align__(16) char smem_raw[];
    u64*   w2_s   = (u64*)smem_raw;                                  // 128KB
    float* xstage = (float*)(w2_s + W2_U64);                         // 84KB
    float* fi_s   = xstage + XSTG_FLOATS;                            // 2048
    float* fo_s   = fi_s + DDIM;                                     // 16
    float* b_s    = fo_s + NEXP;                                     // 16
    float* z_s    = b_s + NEXP;                                      // 14

    // --- noise factors ---
    for (int i = threadIdx.x; i < DDIM; i += BLOCK_MAIN) fi_s[i] = fnoise(ei[i]);
    if (threadIdx.x < NEXP) {
        float fo = fnoise(eo[threadIdx.x]);
        fo_s[threadIdx.x] = fo;
        b_s[threadIdx.x] = b[threadIdx.x] + sb[threadIdx.x] * fo;
    }
    __syncthreads();

    // --- noisy weights into swizzled pair-interleaved SMEM ---
    for (int it = threadIdx.x; it < W2_U64; it += BLOCK_MAIN) {
        int P = it >> 11;            // expert pair
        int d = it & (DDIM - 1);
        int e0 = 2 * P, e1 = 2 * P + 1;
        float fi = fi_s[d];
        float a0 = w[e0 * DDIM + d] + sw[e0 * DDIM + d] * fo_s[e0] * fi;
        float a1 = w[e1 * DDIM + d] + sw[e1 * DDIM + d] * fo_s[e1] * fi;
        int hc = d >> 6, j = (d >> 2) & 15, q = d & 3;
        int h = P >> 2, p = P & 3;
        int idx = hc * 512 + h * 256 + (p * 2 + (q >> 1)) * 32 + j * 2 + (q & 1);
        w2_s[idx] = pack2(a0, a1);
    }
    __syncthreads();

    const int lane = threadIdx.x & 31;
    const int wid  = threadIdx.x >> 5;
    const int gw   = blockIdx.x * WARPS_CTA + wid;   // group id == warp id
    const int j    = lane & 15;
    const int h    = lane >> 4;

    float* warp_stg = xstage + wid * (STAGES * STG_FLOATS);
    float* idx_out  = out + (size_t)NTOK * NEXP;

    if (gw < NGRP) {
        const int t0 = gw * TOK_W;
        const float* xg = x + (size_t)t0 * DDIM;
        unsigned stg_u32 = smem_u32(warp_stg);

        // prime 3 stages with half-chunks 0..2
        #pragma unroll
        for (int s = 0; s < STAGES; s++) {
            #pragma unroll
            for (int tp = 0; tp < 4; tp++)
                cp16(stg_u32 + s * 2048 + (tp * 2 + h) * 256 + j * 16,
                     xg + (tp * 2 + h) * DDIM + s * 64 + j * 4);
            cp_commit();
        }

        u64 acc[TOK_W][4];
        #pragma unroll
        for (int t = 0; t < TOK_W; t++)
            #pragma unroll
            for (int p = 0; p < 4; p++) acc[t][p] = 0ULL;

        int stage = 0;
        #pragma unroll 1
        for (int hc = 0; hc < NHC; hc++) {
            cp_wait2();   // half-chunk hc resident

            // hoist ALL w for this half-chunk: 8 conflict-free LDS.128
            const u64* wb2 = w2_s + hc * 512 + h * 256 + j * 2;
            u64 wv[4][4];
            #pragma unroll
            for (int k = 0; k < 8; k++) {
                ulonglong2 u = *(const ulonglong2*)(wb2 + k * 32);
                wv[k >> 1][(k & 1) * 2 + 0] = u.x;
                wv[k >> 1][(k & 1) * 2 + 1] = u.y;
            }

            const float* xs = warp_stg + stage * STG_FLOATS + j * 4;
            #pragma unroll
            for (int t = 0; t < TOK_W; t++) {
                float4 xa = *(const float4*)(xs + t * 64);
                u64 xk0 = pack2(xa.x, xa.x);
                u64 xk1 = pack2(xa.y, xa.y);
                u64 xk2 = pack2(xa.z, xa.z);
                u64 xk3 = pack2(xa.w, xa.w);
                #pragma unroll
                for (int p = 0; p < 4; p++) {
                    ffma2(acc[t][p], xk0, wv[p][0]);
                    ffma2(acc[t][p], xk1, wv[p][1]);
                    ffma2(acc[t][p], xk2, wv[p][2]);
                    ffma2(acc[t][p], xk3, wv[p][3]);
                }
            }

            // refill this stage with half-chunk hc+3
            if (hc < NHC - STAGES) {
                #pragma unroll
                for (int tp = 0; tp < 4; tp++)
                    cp16(stg_u32 + stage * 2048 + (tp * 2 + h) * 256 + j * 16,
                         xg + (tp * 2 + h) * DDIM + (hc + 3) * 64 + j * 4);
            }
            cp_commit();   // uniform commit keeps wait_group algebra exact
            stage = (stage == STAGES - 1) ? 0 : stage + 1;
        }
        cp_wait0();   // drain before reusing the stage as scratch

        // half-warp butterfly d-reduction (halves are independent: xor<=8)
        #pragma unroll
        for (int t = 0; t < TOK_W; t++)
            #pragma unroll
            for (int p = 0; p < 4; p++) {
                u64 s = acc[t][p];
                s = addx2(s, __shfl_xor_sync(0xffffffffu, s, 8));
                s = addx2(s, __shfl_xor_sync(0xffffffffu, s, 4));
                s = addx2(s, __shfl_xor_sync(0xffffffffu, s, 2));
                s = addx2(s, __shfl_xor_sync(0xffffffffu, s, 1));
                acc[t][p] = s;
            }

        // cross-half exchange through this warp's retired stage memory
        u64* red = (u64*)warp_stg;      // 64 u64 = 512B used
        if (j == 0) {                   // lanes 0 and 16 hold full half-sums
            ulonglong2* r2 = (ulonglong2*)red;
            #pragma unroll
            for (int t = 0; t < TOK_W; t++)
                #pragma unroll
                for (int pp = 0; pp < 2; pp++)
                    r2[h * 16 + t * 2 + pp] =
                        make_ulonglong2(acc[t][2 * pp], acc[t][2 * pp + 1]);
        }
        __syncwarp();

        const int town = lane >> 2;     // this lane's token
        const int q    = lane & 3;      // this lane's 4-expert slice
        const ulonglong2* r2 = (const ulonglong2*)red;
        float v[NEXP];
        #pragma unroll
        for (int h2 = 0; h2 < 2; h2++)
            #pragma unroll
            for (int pp = 0; pp < 2; pp++) {
                ulonglong2 u = r2[h2 * 16 + town * 2 + pp];
                float2 a = unpack64(u.x), c = unpack64(u.y);
                v[h2 * 8 + pp * 4 + 0] = a.x;
                v[h2 * 8 + pp * 4 + 1] = a.y;
                v[h2 * 8 + pp * 4 + 2] = c.x;
                v[h2 * 8 + pp * 4 + 3] = c.y;
            }

        // top-2 + softmax + z for this lane's token
        float m1 = -1e30f, m2 = -1e30f;
        int i1 = 0, i2 = 0;
        #pragma unroll
        for (int e = 0; e < NEXP; e++) {
            float le = v[e] + b_s[e];
            if (le > m1)      { m2 = m1; i2 = i1; m1 = le; i1 = e; }
            else if (le > m2) { m2 = le; i2 = e; }
        }
        float ez = __expf(m2 - m1);
        float rz = 1.0f / (1.0f + ez);
        float p1 = rz, p2 = ez * rz;

        const int tok = t0 + town;
        const int e0 = q * 4;
        float4 o4;
        o4.x = (e0 + 0 == i1) ? p1 : ((e0 + 0 == i2) ? p2 : 0.0f);
        o4.y = (e0 + 1 == i1) ? p1 : ((e0 + 1 == i2) ? p2 : 0.0f);
        o4.z = (e0 + 2 == i1) ? p1 : ((e0 + 2 == i2) ? p2 : 0.0f);
        o4.w = (e0 + 3 == i1) ? p1 : ((e0 + 3 == i2) ? p2 : 0.0f);
        *(float4*)(out + (size_t)tok * NEXP + e0) = o4;
        if (q == 0)
            *(float2*)(idx_out + (size_t)tok * 2) =
                make_float2((float)i1, (float)i2);

        float lse = m1 + log1pf(ez);
        float zl = (q == 0) ? lse * lse : 0.0f;
        #pragma unroll
        for (int k = 16; k > 0; k >>= 1)
            zl += __shfl_xor_sync(0xffffffffu, zl, k);
        if (lane == 0) z_s[wid] = zl;
    } else {
        if (lane == 0) z_s[wid] = 0.0f;
    }

    // --- fused z-loss reduction: CTA partial, then last CTA finishes ---
    __syncthreads();
    __shared__ unsigned int s_last;
    if (threadIdx.x == 0) {
        float a = 0.0f;
        #pragma unroll
        for (int i = 0; i < WARPS_CTA; i++) a += z_s[i];
        g_zp[blockIdx.x] = a;
        __threadfence();
        unsigned int ticket = atomicAdd(&g_ctr, 1u);
        s_last = (ticket == GRID_MAIN - 1) ? 1u : 0u;
    }
    __syncthreads();
    if (s_last && wid == 0) {
        float a = 0.0f;
        for (int i = lane; i < GRID_MAIN; i += 32) a += __ldcg(&g_zp[i]);
        #pragma unroll
        for (int k = 16; k > 0; k >>= 1)
            a += __shfl_xor_sync(0xffffffffu, a, k);
        if (lane == 0) {
            out[(size_t)NTOK * NEXP + (size_t)NTOK * 2] = a * (1.0f / (float)NTOK);
            g_ctr = 0;   // reset for next launch / graph replay
        }
    }
}

// ---------------------------------------------------------------------------
extern "C" void kernel_launch(void* const* d_in, const int* in_sizes, int n_in,
                              void* d_out, int out_size) {
    const float* x  = (const float*)d_in[0];  // mh_output [4,4096,2048]
    const float* w  = (const float*)d_in[1];  // weight [16,2048]
    const float* sw = (const float*)d_in[2];  // sigma_weight
    const float* b  = (const float*)d_in[3];  // bias [16]
    const float* sb = (const float*)d_in[4];  // sigma_bias
    const float* ei = (const float*)d_in[5];  // eps_in [2048]
    const float* eo = (const float*)d_in[6];  // eps_out [16]
    float* out = (float*)d_out;

    const size_t smem_bytes = (size_t)W2_U64 * 8
                            + (size_t)XSTG_FLOATS * 4
                            + (size_t)(DDIM + 2 * NEXP + WARPS_CTA) * sizeof(float)
                            + 64;
    cudaFuncSetAttribute(router_kernel,
                         cudaFuncAttributeMaxDynamicSharedMemorySize,
                         (int)smem_bytes);
    router_kernel<<<GRID_MAIN, BLOCK_MAIN, smem_bytes>>>(x, w, sw, b, sb, ei, eo, out);
}